// round 7
// baseline (speedup 1.0000x reference)
#include <cuda_runtime.h>
#include <cuda_fp16.h>
#include <cstdint>

#define BATCH 1024
#define FDIM 39
#define DDIM 64
#define ODIM 128
#define G 4
#define KT 32
#define THREADS 512

// ---------------- scratch ----------------
__device__ float g_X1[BATCH * ODIM * DDIM];
__device__ float g_X2[BATCH * ODIM * DDIM];
__device__ alignas(16) __half g_W1hi[ODIM * 1536], g_W1lo[ODIM * 1536];
__device__ alignas(16) __half g_W2hi[ODIM * 4992], g_W2lo[ODIM * 4992];
__device__ alignas(16) __half g_W3hi[ODIM * 4992], g_W3lo[ODIM * 4992];

// ---------------- smem layout ----------------
// x0s: G*39*64 f32 = 39936
// xis: G*32*64 f32 = 32768 (L2/3 only)
// 3 stages: Ahi 128x80 | Alo 128x80 | B 32x528  (37376 each)
#define A_STRIDE 80
#define B_STRIDE 528
#define OFF_AHI 0
#define OFF_ALO 10240
#define OFF_B   20480
#define STG_SZ  37376
#define OFF_X0S 0
#define X0S_SZ  (G * FDIM * DDIM * 4)        // 39936
#define XIS_SZ  (G * KT * DDIM * 4)          // 32768
#define SMEM_L1  (X0S_SZ + 3 * STG_SZ)                // 152064
#define SMEM_L23 (X0S_SZ + XIS_SZ + 3 * STG_SZ)       // 184832

__device__ __forceinline__ uint32_t smem_u32(const void* p) {
    uint32_t a;
    asm("{ .reg .u64 t; cvta.to.shared.u64 t, %1; cvt.u32.u64 %0, t; }" : "=r"(a) : "l"(p));
    return a;
}

#define CP_ASYNC16(dst, src) \
    asm volatile("cp.async.cg.shared.global [%0], [%1], 16;" :: "r"(dst), "l"(src))
#define CP_COMMIT() asm volatile("cp.async.commit_group;")
#define CP_WAIT0()  asm volatile("cp.async.wait_group 0;")

#define LDSM_X4(r, addr) \
    asm volatile("ldmatrix.sync.aligned.m8n8.x4.shared.b16 {%0,%1,%2,%3}, [%4];" \
        : "=r"((r)[0]), "=r"((r)[1]), "=r"((r)[2]), "=r"((r)[3]) : "r"(addr))
#define LDSM_X4T(r, addr) \
    asm volatile("ldmatrix.sync.aligned.m8n8.x4.trans.shared.b16 {%0,%1,%2,%3}, [%4];" \
        : "=r"((r)[0]), "=r"((r)[1]), "=r"((r)[2]), "=r"((r)[3]) : "r"(addr))

__device__ __forceinline__ void mma16816(float* c, const uint32_t* a, const uint32_t* b) {
    asm volatile("mma.sync.aligned.m16n8k16.row.col.f32.f16.f16.f32 "
        "{%0,%1,%2,%3}, {%4,%5,%6,%7}, {%8,%9}, {%0,%1,%2,%3};"
        : "+f"(c[0]), "+f"(c[1]), "+f"(c[2]), "+f"(c[3])
        : "r"(a[0]), "r"(a[1]), "r"(a[2]), "r"(a[3]), "r"(b[0]), "r"(b[1]));
}

// stage W hi/lo tiles via cp.async. 512 threads: 4 per o-row, 16B each.
template <int CPAD_>
__device__ __forceinline__ void stage_w(uint32_t sb, const __half* Whi,
                                        const __half* Wlo, int c0, int tid) {
    const int wrow = tid >> 2, wq = tid & 3;
    const char* sh = (const char*)(Whi + (size_t)wrow * CPAD_ + c0) + wq * 16;
    const char* sl = (const char*)(Wlo + (size_t)wrow * CPAD_ + c0) + wq * 16;
    CP_ASYNC16(sb + OFF_AHI + wrow * A_STRIDE + wq * 16, sh);
    CP_ASYNC16(sb + OFF_ALO + wrow * A_STRIDE + wq * 16, sl);
    CP_COMMIT();
}

// MMA over one staged tile: 2 terms (Whi*B, Wlo*B), distance-8 accum chains
__device__ __forceinline__ void mma_tile(uint32_t sb, int warp_m, int warp_n,
                                         int lr, int lc, float acc[2][8][4]) {
#pragma unroll
    for (int kb = 0; kb < 2; ++kb) {
        uint32_t ah[2][4], al[2][4];
#pragma unroll
        for (int mf = 0; mf < 2; ++mf) {
            const uint32_t aoff = (warp_m * 32 + mf * 16 + lr) * A_STRIDE + kb * 32 + lc * 16;
            LDSM_X4(ah[mf], sb + OFF_AHI + aoff);
            LDSM_X4(al[mf], sb + OFF_ALO + aoff);
        }
#pragma unroll
        for (int ip = 0; ip < 2; ++ip) {
            uint32_t bb[2][4];
#pragma unroll
            for (int ii = 0; ii < 2; ++ii) {
                const int i = ip * 2 + ii;
                const uint32_t boff = (kb * 16 + lr) * B_STRIDE +
                                      (warp_n * 64 + i * 16) * 2 + lc * 16;
                LDSM_X4T(bb[ii], sb + OFF_B + boff);
            }
#pragma unroll
            for (int mf = 0; mf < 2; ++mf)
#pragma unroll
                for (int ii = 0; ii < 2; ++ii) {
                    mma16816(acc[mf][(ip * 2 + ii) * 2],     ah[mf], bb[ii]);
                    mma16816(acc[mf][(ip * 2 + ii) * 2 + 1], ah[mf], bb[ii] + 2);
                }
#pragma unroll
            for (int mf = 0; mf < 2; ++mf)
#pragma unroll
                for (int ii = 0; ii < 2; ++ii) {
                    mma16816(acc[mf][(ip * 2 + ii) * 2],     al[mf], bb[ii]);
                    mma16816(acc[mf][(ip * 2 + ii) * 2 + 1], al[mf], bb[ii] + 2);
                }
        }
    }
}

__device__ __forceinline__ void epilogue(float acc[2][8][4], const float* bias,
                                         float* Xout, float* out, int out_off,
                                         int b0, int warp_m, int warp_n, int lane) {
    const int g = warp_n;
#pragma unroll
    for (int mf = 0; mf < 2; ++mf) {
        const int r0 = warp_m * 32 + mf * 16 + (lane >> 2);
        const int r1 = r0 + 8;
        const float bv0 = bias[r0], bv1 = bias[r1];
        float s0 = 0.f, s1 = 0.f;
#pragma unroll
        for (int nf = 0; nf < 8; ++nf) {
            float* c = acc[mf][nf];
            s0 += c[0] + c[1];
            s1 += c[2] + c[3];
            if (Xout) {
                const int d = nf * 8 + (lane & 3) * 2;
                float2 v0 = { c[0] + bv0, c[1] + bv0 };
                float2 v1 = { c[2] + bv1, c[3] + bv1 };
                *(float2*)(Xout + (size_t)(b0 + g) * ODIM * DDIM + r0 * DDIM + d) = v0;
                *(float2*)(Xout + (size_t)(b0 + g) * ODIM * DDIM + r1 * DDIM + d) = v1;
            }
        }
        s0 += __shfl_xor_sync(0xffffffffu, s0, 1);
        s0 += __shfl_xor_sync(0xffffffffu, s0, 2);
        s1 += __shfl_xor_sync(0xffffffffu, s1, 1);
        s1 += __shfl_xor_sync(0xffffffffu, s1, 2);
        if ((lane & 3) == 0) {
            out[(size_t)(b0 + g) * 384 + out_off + r0] = s0 + 64.f * bv0;
            out[(size_t)(b0 + g) * 384 + out_off + r1] = s1 + 64.f * bv1;
        }
    }
}

// ---------------- W pre-split (fp32 -> fp16 hi/lo, zero padded) ----------------
__global__ void split_w_kernel(const float* __restrict__ W, __half* __restrict__ hi,
                               __half* __restrict__ lo, int C, int Cpad) {
    int i = blockIdx.x * 256 + threadIdx.x;
    if (i >= ODIM * Cpad) return;
    int o = i / Cpad, cp = i - o * Cpad;
    float w = (cp < C) ? W[o * C + cp] : 0.f;
    __half h = __float2half_rn(w);
    hi[i] = h;
    lo[i] = __float2half_rn(w - __half2float(h));
}

// ---------------- Layer 1: Xi == X0, both operands in smem ----------------
__global__ __launch_bounds__(THREADS, 1) void cin_l1(
    const float* __restrict__ X0,
    const __half* __restrict__ Whi, const __half* __restrict__ Wlo,
    const float* __restrict__ bias, float* __restrict__ Xout, float* __restrict__ out)
{
    extern __shared__ char smem[];
    constexpr int CPAD_ = 1536, C_ = 1521, NT = CPAD_ / KT;   // 48 tiles

    const int tid = threadIdx.x, wid = tid >> 5, lane = tid & 31;
    const int b0 = blockIdx.x * G;
    const int warp_m = wid >> 2, warp_n = wid & 3;
    const int lr = lane & 15, lc = lane >> 4;
    const int n2 = (tid & 127) * 2, kh = tid >> 7;
    const int gg = n2 >> 6, dd = n2 & 63;

    float* x0s = (float*)smem;
    const float* x0_g = x0s + gg * FDIM * DDIM;
    const uint32_t stg = smem_u32(smem + X0S_SZ);

    for (int i = tid; i < G * FDIM * DDIM; i += THREADS)
        x0s[i] = X0[(size_t)b0 * FDIM * DDIM + i];

    float acc[2][8][4];
#pragma unroll
    for (int a = 0; a < 2; ++a)
#pragma unroll
        for (int b = 0; b < 8; ++b)
#pragma unroll
            for (int c = 0; c < 4; ++c) acc[a][b][c] = 0.f;

    auto gen = [&](int t) {
        const uint32_t sb = stg + (t % 3) * STG_SZ;
        char* sbc = smem + X0S_SZ + (t % 3) * STG_SZ;
        const int c0 = t * KT;
        stage_w<CPAD_>(sb, Whi, Wlo, c0, tid);
#pragma unroll
        for (int j = 0; j < 8; ++j) {
            const int k = kh * 8 + j;
            const int c = c0 + k;
            float p0 = 0.f, p1 = 0.f;
            if (c < C_) {
                const int h = c / FDIM;
                const int m = c - h * FDIM;
                const float2 xv = *(const float2*)(x0_g + h * DDIM + dd);
                const float2 iv = *(const float2*)(x0_g + m * DDIM + dd);
                p0 = xv.x * iv.x; p1 = xv.y * iv.y;
            }
            __half2 hp = __floats2half2_rn(p0, p1);
            *(uint32_t*)(sbc + OFF_B + k * B_STRIDE + n2 * 2) = *(uint32_t*)&hp;
        }
    };

    __syncthreads();            // x0s ready
    gen(0); gen(1);
    CP_WAIT0();
    __syncthreads();

    for (int t = 0; t < NT; ++t) {
        mma_tile(stg + (t % 3) * STG_SZ, warp_m, warp_n, lr, lc, acc);
        CP_WAIT0();             // W group for tile t+1 (issued at iter t-1)
        __syncthreads();
        if (t + 2 < NT) gen(t + 2);
    }
    epilogue(acc, bias, Xout, out, 0, b0, warp_m, warp_n, lane);
}

// ---------------- Layers 2/3: mb-outer, Xi m-block staged in smem ----------------
__global__ __launch_bounds__(THREADS, 1) void cin_l23(
    const float* __restrict__ X0, const float* __restrict__ Xi,
    const __half* __restrict__ Whi, const __half* __restrict__ Wlo,
    const float* __restrict__ bias, float* __restrict__ Xout,
    float* __restrict__ out, int out_off)
{
    extern __shared__ char smem[];
    constexpr int CPAD_ = 4992, M_ = 128;

    const int tid = threadIdx.x, wid = tid >> 5, lane = tid & 31;
    const int b0 = blockIdx.x * G;
    const int warp_m = wid >> 2, warp_n = wid & 3;
    const int lr = lane & 15, lc = lane >> 4;
    const int n2 = (tid & 127) * 2, kh = tid >> 7;
    const int gg = n2 >> 6, dd = n2 & 63;

    float* x0s = (float*)smem;
    float* xis = (float*)(smem + X0S_SZ);
    const float* x0_g = x0s + gg * FDIM * DDIM;
    const float* xi_g = xis + gg * KT * DDIM;
    const uint32_t stg = smem_u32(smem + X0S_SZ + XIS_SZ);
    const uint32_t xis_u32 = smem_u32(xis);

    for (int i = tid; i < G * FDIM * DDIM; i += THREADS)
        x0s[i] = X0[(size_t)b0 * FDIM * DDIM + i];

    float acc[2][8][4];
#pragma unroll
    for (int a = 0; a < 2; ++a)
#pragma unroll
        for (int b = 0; b < 8; ++b)
#pragma unroll
            for (int c = 0; c < 4; ++c) acc[a][b][c] = 0.f;

    auto gen = [&](int mb, int h, int buf) {
        const uint32_t sb = stg + buf * STG_SZ;
        char* sbc = smem + X0S_SZ + XIS_SZ + buf * STG_SZ;
        const int c0 = h * M_ + mb * KT;
        stage_w<CPAD_>(sb, Whi, Wlo, c0, tid);
        const float2 xv = *(const float2*)(x0_g + h * DDIM + dd);
#pragma unroll
        for (int j = 0; j < 8; ++j) {
            const int k = kh * 8 + j;
            const float2 iv = *(const float2*)(xi_g + k * DDIM + dd);
            __half2 hp = __floats2half2_rn(xv.x * iv.x, xv.y * iv.y);
            *(uint32_t*)(sbc + OFF_B + k * B_STRIDE + n2 * 2) = *(uint32_t*)&hp;
        }
    };

    __syncthreads();            // x0s ready
    for (int mb = 0; mb < 4; ++mb) {
        // stage Xi m-block: G*32*64 f32 = 2048 x 16B, 4 per thread
#pragma unroll
        for (int it = 0; it < 4; ++it) {
            const int idx = it * THREADS + tid;
            const int g = idx >> 9, rem = idx & 511;
            const float* src = Xi + (size_t)(b0 + g) * M_ * DDIM + mb * KT * DDIM + rem * 4;
            CP_ASYNC16(xis_u32 + idx * 16, src);
        }
        CP_COMMIT();
        CP_WAIT0();
        __syncthreads();

        gen(mb, 0, 0); gen(mb, 1, 1);
        CP_WAIT0();
        __syncthreads();

        for (int h = 0; h < FDIM; ++h) {
            mma_tile(stg + (h % 3) * STG_SZ, warp_m, warp_n, lr, lc, acc);
            CP_WAIT0();
            __syncthreads();
            if (h + 2 < FDIM) gen(mb, h + 2, (h + 2) % 3);
        }
    }
    epilogue(acc, bias, Xout, out, out_off, b0, warp_m, warp_n, lane);
}

// ---------------- launch ----------------
extern "C" void kernel_launch(void* const* d_in, const int* in_sizes, int n_in,
                              void* d_out, int out_size)
{
    const float* X0 = (const float*)d_in[0];
    const float* W1 = (const float*)d_in[1];
    const float* b1 = (const float*)d_in[2];
    const float* W2 = (const float*)d_in[3];
    const float* b2 = (const float*)d_in[4];
    const float* W3 = (const float*)d_in[5];
    const float* b3 = (const float*)d_in[6];
    float* out = (float*)d_out;

    float *X1p, *X2p;
    __half *W1h, *W1l, *W2h, *W2l, *W3h, *W3l;
    cudaGetSymbolAddress((void**)&X1p, g_X1);
    cudaGetSymbolAddress((void**)&X2p, g_X2);
    cudaGetSymbolAddress((void**)&W1h, g_W1hi);
    cudaGetSymbolAddress((void**)&W1l, g_W1lo);
    cudaGetSymbolAddress((void**)&W2h, g_W2hi);
    cudaGetSymbolAddress((void**)&W2l, g_W2lo);
    cudaGetSymbolAddress((void**)&W3h, g_W3hi);
    cudaGetSymbolAddress((void**)&W3l, g_W3lo);

    cudaFuncSetAttribute(cin_l1,  cudaFuncAttributeMaxDynamicSharedMemorySize, SMEM_L1);
    cudaFuncSetAttribute(cin_l23, cudaFuncAttributeMaxDynamicSharedMemorySize, SMEM_L23);

    split_w_kernel<<<(ODIM * 1536 + 255) / 256, 256>>>(W1, W1h, W1l, 1521, 1536);
    split_w_kernel<<<(ODIM * 4992 + 255) / 256, 256>>>(W2, W2h, W2l, 4992, 4992);
    split_w_kernel<<<(ODIM * 4992 + 255) / 256, 256>>>(W3, W3h, W3l, 4992, 4992);

    cin_l1 <<<BATCH / G, THREADS, SMEM_L1 >>>(X0, W1h, W1l, b1, X1p, out);
    cin_l23<<<BATCH / G, THREADS, SMEM_L23>>>(X0, X1p, W2h, W2l, b2, X2p, out, 128);
    cin_l23<<<BATCH / G, THREADS, SMEM_L23>>>(X0, X2p, W3h, W3l, b3, nullptr, out, 256);
}

// round 9
// speedup vs baseline: 1.5580x; 1.5580x over previous
#include <cuda_runtime.h>
#include <cuda_fp16.h>
#include <cstdint>

#define BATCH 1024
#define FDIM 39
#define DDIM 64
#define ODIM 128
#define G 2
#define KT 64
#define THREADS 256

// ---------------- scratch ----------------
__device__ float g_X1[BATCH * ODIM * DDIM];
__device__ float g_X2[BATCH * ODIM * DDIM];
__device__ alignas(16) __half g_W1[ODIM * 1536];
__device__ alignas(16) __half g_W2[ODIM * 4992];
__device__ alignas(16) __half g_W3[ODIM * 4992];

// ---------------- smem layout ----------------
// stage (x2): A 128x144B | B 64x272B  = 35840 each
// l1:  x0s 19968 + 2*35840 = 91648
// l23: xis 32768 + 2*35840 = 104448
#define A_STRIDE 144
#define B_STRIDE 272
#define OFF_A 0
#define OFF_B 18432
#define STG_SZ 35840
#define X0S_SZ (G * FDIM * DDIM * 4)   // 19968
#define XIS_SZ (G * KT * DDIM * 4)     // 32768
#define SMEM_L1  (X0S_SZ + 2 * STG_SZ)  // 91648
#define SMEM_L23 (XIS_SZ + 2 * STG_SZ)  // 104448

__device__ __forceinline__ uint32_t smem_u32(const void* p) {
    uint32_t a;
    asm("{ .reg .u64 t; cvta.to.shared.u64 t, %1; cvt.u32.u64 %0, t; }" : "=r"(a) : "l"(p));
    return a;
}

#define CP_ASYNC16(dst, src) \
    asm volatile("cp.async.cg.shared.global [%0], [%1], 16;" :: "r"(dst), "l"(src))
#define CP_COMMIT() asm volatile("cp.async.commit_group;")
#define CP_WAIT0()  asm volatile("cp.async.wait_group 0;")

#define LDSM_X4(r, addr) \
    asm volatile("ldmatrix.sync.aligned.m8n8.x4.shared.b16 {%0,%1,%2,%3}, [%4];" \
        : "=r"((r)[0]), "=r"((r)[1]), "=r"((r)[2]), "=r"((r)[3]) : "r"(addr))
#define LDSM_X4T(r, addr) \
    asm volatile("ldmatrix.sync.aligned.m8n8.x4.trans.shared.b16 {%0,%1,%2,%3}, [%4];" \
        : "=r"((r)[0]), "=r"((r)[1]), "=r"((r)[2]), "=r"((r)[3]) : "r"(addr))

__device__ __forceinline__ void mma16816(float* c, const uint32_t* a, const uint32_t* b) {
    asm volatile("mma.sync.aligned.m16n8k16.row.col.f32.f16.f16.f32 "
        "{%0,%1,%2,%3}, {%4,%5,%6,%7}, {%8,%9}, {%0,%1,%2,%3};"
        : "+f"(c[0]), "+f"(c[1]), "+f"(c[2]), "+f"(c[3])
        : "r"(a[0]), "r"(a[1]), "r"(a[2]), "r"(a[3]), "r"(b[0]), "r"(b[1]));
}

// stage W tile (single fp16 plane): 128 rows x 128B; 2 threads/row, 64B each
template <int CPAD_>
__device__ __forceinline__ void stage_w(uint32_t sb, const __half* W, int c0, int tid) {
    const int wrow = tid >> 1, whalf = tid & 1;
    const char* src = (const char*)(W + (size_t)wrow * CPAD_ + c0) + whalf * 64;
    const uint32_t dst = sb + OFF_A + wrow * A_STRIDE + whalf * 64;
#pragma unroll
    for (int q = 0; q < 4; ++q)
        CP_ASYNC16(dst + q * 16, src + q * 16);
    CP_COMMIT();
}

// MMA over one KT=64 tile: 4 k16 blocks, 16 MMA each (single W term)
__device__ __forceinline__ void mma_tile(uint32_t sb, int warp_m, int warp_n,
                                         int lr, int lc, float acc[2][8][4]) {
#pragma unroll
    for (int kb = 0; kb < 4; ++kb) {
        uint32_t ah[2][4];
#pragma unroll
        for (int mf = 0; mf < 2; ++mf) {
            const uint32_t aoff = (warp_m * 32 + mf * 16 + lr) * A_STRIDE + kb * 32 + lc * 16;
            LDSM_X4(ah[mf], sb + OFF_A + aoff);
        }
#pragma unroll
        for (int ip = 0; ip < 2; ++ip) {
            uint32_t bb[2][4];
#pragma unroll
            for (int ii = 0; ii < 2; ++ii) {
                const int i = ip * 2 + ii;
                const uint32_t boff = (kb * 16 + lr) * B_STRIDE +
                                      (warp_n * 64 + i * 16) * 2 + lc * 16;
                LDSM_X4T(bb[ii], sb + OFF_B + boff);
            }
#pragma unroll
            for (int mf = 0; mf < 2; ++mf)
#pragma unroll
                for (int ii = 0; ii < 2; ++ii) {
                    mma16816(acc[mf][(ip * 2 + ii) * 2],     ah[mf], bb[ii]);
                    mma16816(acc[mf][(ip * 2 + ii) * 2 + 1], ah[mf], bb[ii] + 2);
                }
        }
    }
}

__device__ __forceinline__ void epilogue(float acc[2][8][4], const float* bias,
                                         float* Xout, float* out, int out_off,
                                         int b0, int warp_m, int warp_n, int lane) {
    const int g = warp_n;
#pragma unroll
    for (int mf = 0; mf < 2; ++mf) {
        const int r0 = warp_m * 32 + mf * 16 + (lane >> 2);
        const int r1 = r0 + 8;
        const float bv0 = bias[r0], bv1 = bias[r1];
        float s0 = 0.f, s1 = 0.f;
#pragma unroll
        for (int nf = 0; nf < 8; ++nf) {
            float* c = acc[mf][nf];
            s0 += c[0] + c[1];
            s1 += c[2] + c[3];
            if (Xout) {
                const int d = nf * 8 + (lane & 3) * 2;
                float2 v0 = { c[0] + bv0, c[1] + bv0 };
                float2 v1 = { c[2] + bv1, c[3] + bv1 };
                *(float2*)(Xout + (size_t)(b0 + g) * ODIM * DDIM + r0 * DDIM + d) = v0;
                *(float2*)(Xout + (size_t)(b0 + g) * ODIM * DDIM + r1 * DDIM + d) = v1;
            }
        }
        s0 += __shfl_xor_sync(0xffffffffu, s0, 1);
        s0 += __shfl_xor_sync(0xffffffffu, s0, 2);
        s1 += __shfl_xor_sync(0xffffffffu, s1, 1);
        s1 += __shfl_xor_sync(0xffffffffu, s1, 2);
        if ((lane & 3) == 0) {
            out[(size_t)(b0 + g) * 384 + out_off + r0] = s0 + 64.f * bv0;
            out[(size_t)(b0 + g) * 384 + out_off + r1] = s1 + 64.f * bv1;
        }
    }
}

// ---------------- W convert (fp32 -> fp16, zero padded) ----------------
__global__ void conv_w_kernel(const float* __restrict__ W, __half* __restrict__ hi,
                              int C, int Cpad) {
    int i = blockIdx.x * 256 + threadIdx.x;
    if (i >= ODIM * Cpad) return;
    int o = i / Cpad, cp = i - o * Cpad;
    hi[i] = __float2half_rn((cp < C) ? W[o * C + cp] : 0.f);
}

// ---------------- Layer 1: Xi == X0, both operands in smem ----------------
__global__ __launch_bounds__(THREADS, 2) void cin_l1(
    const float* __restrict__ X0, const __half* __restrict__ W,
    const float* __restrict__ bias, float* __restrict__ Xout, float* __restrict__ out)
{
    extern __shared__ char smem[];
    constexpr int CPAD_ = 1536, C_ = 1521, NT = CPAD_ / KT;   // 24 tiles

    const int tid = threadIdx.x, wid = tid >> 5, lane = tid & 31;
    const int b0 = blockIdx.x * G;
    const int warp_m = wid >> 1, warp_n = wid & 1;
    const int lr = lane & 15, lc = lane >> 4;
    const int n2 = (tid & 63) * 2, kh = tid >> 6;   // 4 kh groups x 16 k
    const int gg = n2 >> 6, dd = n2 & 63;

    float* x0s = (float*)smem;
    const float* x0_g = x0s + gg * FDIM * DDIM;
    const uint32_t stg = smem_u32(smem + X0S_SZ);

    for (int i = tid; i < G * FDIM * DDIM; i += THREADS)
        x0s[i] = X0[(size_t)b0 * FDIM * DDIM + i];

    float acc[2][8][4];
#pragma unroll
    for (int a = 0; a < 2; ++a)
#pragma unroll
        for (int b = 0; b < 8; ++b)
#pragma unroll
            for (int c = 0; c < 4; ++c) acc[a][b][c] = 0.f;

    auto gen = [&](int t) {
        const uint32_t sb = stg + (t & 1) * STG_SZ;
        char* sbc = smem + X0S_SZ + (t & 1) * STG_SZ;
        const int c0 = t * KT;
        stage_w<CPAD_>(sb, W, c0, tid);
#pragma unroll
        for (int j = 0; j < 16; ++j) {
            const int k = kh * 16 + j;
            const int c = c0 + k;
            float p0 = 0.f, p1 = 0.f;
            if (c < C_) {
                const int h = c / FDIM;
                const int m = c - h * FDIM;
                const float2 xv = *(const float2*)(x0_g + h * DDIM + dd);
                const float2 iv = *(const float2*)(x0_g + m * DDIM + dd);
                p0 = xv.x * iv.x; p1 = xv.y * iv.y;
            }
            __half2 hp = __floats2half2_rn(p0, p1);
            *(uint32_t*)(sbc + OFF_B + k * B_STRIDE + n2 * 2) = *(uint32_t*)&hp;
        }
    };

    __syncthreads();          // x0s ready
    gen(0);
    CP_WAIT0();
    __syncthreads();

    for (int t = 0; t < NT; ++t) {
        if (t + 1 < NT) gen(t + 1);
        mma_tile(stg + (t & 1) * STG_SZ, warp_m, warp_n, lr, lc, acc);
        CP_WAIT0();
        __syncthreads();
    }
    epilogue(acc, bias, Xout, out, 0, b0, warp_m, warp_n, lane);
}

// ---------------- Layers 2/3: mb-outer, Xi m-block in smem, x0 reg-prefetch ----------------
__global__ __launch_bounds__(THREADS, 2) void cin_l23(
    const float* __restrict__ X0, const float* __restrict__ Xi,
    const __half* __restrict__ W,
    const float* __restrict__ bias, float* __restrict__ Xout,
    float* __restrict__ out, int out_off)
{
    extern __shared__ char smem[];
    constexpr int CPAD_ = 4992, M_ = 128;

    const int tid = threadIdx.x, wid = tid >> 5, lane = tid & 31;
    const int b0 = blockIdx.x * G;
    const int warp_m = wid >> 1, warp_n = wid & 1;
    const int lr = lane & 15, lc = lane >> 4;
    const int n2 = (tid & 63) * 2, kh = tid >> 6;
    const int gg = n2 >> 6, dd = n2 & 63;

    float* xis = (float*)smem;
    const float* xi_g = xis + gg * KT * DDIM;
    const uint32_t stg = smem_u32(smem + XIS_SZ);
    const uint32_t xis_u32 = smem_u32(xis);
    const float* x0_row = X0 + (size_t)(b0 + gg) * FDIM * DDIM + dd;

    float acc[2][8][4];
#pragma unroll
    for (int a = 0; a < 2; ++a)
#pragma unroll
        for (int b = 0; b < 8; ++b)
#pragma unroll
            for (int c = 0; c < 4; ++c) acc[a][b][c] = 0.f;

    auto x0ld = [&](int h) -> float2 {
        return __ldg((const float2*)(x0_row + h * DDIM));
    };

    auto gen = [&](int mb, int h, int buf, float2 xv) {
        const uint32_t sb = stg + buf * STG_SZ;
        char* sbc = smem + XIS_SZ + buf * STG_SZ;
        const int c0 = h * M_ + mb * KT;
        stage_w<CPAD_>(sb, W, c0, tid);
#pragma unroll
        for (int j = 0; j < 16; ++j) {
            const int k = kh * 16 + j;
            const float2 iv = *(const float2*)(xi_g + k * DDIM + dd);
            __half2 hp = __floats2half2_rn(xv.x * iv.x, xv.y * iv.y);
            *(uint32_t*)(sbc + OFF_B + k * B_STRIDE + n2 * 2) = *(uint32_t*)&hp;
        }
    };

    for (int mb = 0; mb < 2; ++mb) {
        __syncthreads();   // prior mb's gens done reading xis (and tiles done)
        // stage Xi m-block: G*64*64 f32 = 2048 x 16B, 8 per thread
#pragma unroll
        for (int it = 0; it < 8; ++it) {
            const int idx = it * THREADS + tid;
            const int g = idx >> 10, rem = idx & 1023;
            const float* src = Xi + (size_t)(b0 + g) * M_ * DDIM + mb * KT * DDIM + rem * 4;
            CP_ASYNC16(xis_u32 + idx * 16, src);
        }
        CP_COMMIT();
        CP_WAIT0();
        __syncthreads();

        float2 xv_n = x0ld(0);
        gen(mb, 0, 0, xv_n);
        xv_n = x0ld(1);
        CP_WAIT0();
        __syncthreads();

        for (int h = 0; h < FDIM; ++h) {
            if (h + 1 < FDIM) {
                const float2 xv_c = xv_n;
                if (h + 2 < FDIM) xv_n = x0ld(h + 2);
                gen(mb, h + 1, (h + 1) & 1, xv_c);
            }
            mma_tile(stg + (h & 1) * STG_SZ, warp_m, warp_n, lr, lc, acc);
            CP_WAIT0();
            __syncthreads();
        }
    }
    epilogue(acc, bias, Xout, out, out_off, b0, warp_m, warp_n, lane);
}

// ---------------- launch ----------------
extern "C" void kernel_launch(void* const* d_in, const int* in_sizes, int n_in,
                              void* d_out, int out_size)
{
    const float* X0 = (const float*)d_in[0];
    const float* W1 = (const float*)d_in[1];
    const float* b1 = (const float*)d_in[2];
    const float* W2 = (const float*)d_in[3];
    const float* b2 = (const float*)d_in[4];
    const float* W3 = (const float*)d_in[5];
    const float* b3 = (const float*)d_in[6];
    float* out = (float*)d_out;

    float *X1p, *X2p;
    __half *W1h, *W2h, *W3h;
    cudaGetSymbolAddress((void**)&X1p, g_X1);
    cudaGetSymbolAddress((void**)&X2p, g_X2);
    cudaGetSymbolAddress((void**)&W1h, g_W1);
    cudaGetSymbolAddress((void**)&W2h, g_W2);
    cudaGetSymbolAddress((void**)&W3h, g_W3);

    cudaFuncSetAttribute(cin_l1,  cudaFuncAttributeMaxDynamicSharedMemorySize, SMEM_L1);
    cudaFuncSetAttribute(cin_l23, cudaFuncAttributeMaxDynamicSharedMemorySize, SMEM_L23);

    conv_w_kernel<<<(ODIM * 1536 + 255) / 256, 256>>>(W1, W1h, 1521, 1536);
    conv_w_kernel<<<(ODIM * 4992 + 255) / 256, 256>>>(W2, W2h, 4992, 4992);
    conv_w_kernel<<<(ODIM * 4992 + 255) / 256, 256>>>(W3, W3h, 4992, 4992);

    cin_l1 <<<BATCH / G, THREADS, SMEM_L1 >>>(X0, W1h, b1, X1p, out);
    cin_l23<<<BATCH / G, THREADS, SMEM_L23>>>(X0, X1p, W2h, b2, X2p, out, 128);
    cin_l23<<<BATCH / G, THREADS, SMEM_L23>>>(X0, X2p, W3h, b3, nullptr, out, 256);
}

// round 10
// speedup vs baseline: 1.6806x; 1.0787x over previous
#include <cuda_runtime.h>
#include <cuda_fp16.h>
#include <cstdint>

#define BATCH 1024
#define FDIM 39
#define DDIM 64
#define ODIM 128
#define G 2
#define KT 64
#define THREADS 256

// ---------------- scratch ----------------
__device__ alignas(16) __half g_X1[BATCH * ODIM * DDIM];
__device__ alignas(16) __half g_X2[BATCH * ODIM * DDIM];
__device__ alignas(16) __half g_W1[ODIM * 1536];
__device__ alignas(16) __half g_W2[ODIM * 4992];
__device__ alignas(16) __half g_W3[ODIM * 4992];

// ---------------- smem layout ----------------
// stage (x2): A 128x144B | B 64x272B = 35840 each
// l1:  x0h (half) 9984 + 2*35840 = 81664
// l23: xis (half) 16384 + 2*35840 = 88064
#define A_STRIDE 144
#define B_STRIDE 272
#define OFF_A 0
#define OFF_B 18432
#define STG_SZ 35840
#define X0H_SZ (G * FDIM * DDIM * 2)   // 9984 (16B aligned)
#define XIS_SZ (G * KT * DDIM * 2)     // 16384
#define SMEM_L1  (X0H_SZ + 2 * STG_SZ)  // 81664
#define SMEM_L23 (XIS_SZ + 2 * STG_SZ)  // 88064

__device__ __forceinline__ uint32_t smem_u32(const void* p) {
    uint32_t a;
    asm("{ .reg .u64 t; cvta.to.shared.u64 t, %1; cvt.u32.u64 %0, t; }" : "=r"(a) : "l"(p));
    return a;
}

#define CP_ASYNC16(dst, src) \
    asm volatile("cp.async.cg.shared.global [%0], [%1], 16;" :: "r"(dst), "l"(src))
#define CP_COMMIT() asm volatile("cp.async.commit_group;")
#define CP_WAIT0()  asm volatile("cp.async.wait_group 0;")

#define LDSM_X4(r, addr) \
    asm volatile("ldmatrix.sync.aligned.m8n8.x4.shared.b16 {%0,%1,%2,%3}, [%4];" \
        : "=r"((r)[0]), "=r"((r)[1]), "=r"((r)[2]), "=r"((r)[3]) : "r"(addr))
#define LDSM_X4T(r, addr) \
    asm volatile("ldmatrix.sync.aligned.m8n8.x4.trans.shared.b16 {%0,%1,%2,%3}, [%4];" \
        : "=r"((r)[0]), "=r"((r)[1]), "=r"((r)[2]), "=r"((r)[3]) : "r"(addr))

__device__ __forceinline__ void mma16816(float* c, const uint32_t* a, const uint32_t* b) {
    asm volatile("mma.sync.aligned.m16n8k16.row.col.f32.f16.f16.f32 "
        "{%0,%1,%2,%3}, {%4,%5,%6,%7}, {%8,%9}, {%0,%1,%2,%3};"
        : "+f"(c[0]), "+f"(c[1]), "+f"(c[2]), "+f"(c[3])
        : "r"(a[0]), "r"(a[1]), "r"(a[2]), "r"(a[3]), "r"(b[0]), "r"(b[1]));
}

// stage W tile (single fp16 plane): 128 rows x 128B; 2 threads/row, 64B each
template <int CPAD_>
__device__ __forceinline__ void stage_w(uint32_t sb, const __half* W, int c0, int tid) {
    const int wrow = tid >> 1, whalf = tid & 1;
    const char* src = (const char*)(W + (size_t)wrow * CPAD_ + c0) + whalf * 64;
    const uint32_t dst = sb + OFF_A + wrow * A_STRIDE + whalf * 64;
#pragma unroll
    for (int q = 0; q < 4; ++q)
        CP_ASYNC16(dst + q * 16, src + q * 16);
    CP_COMMIT();
}

// MMA over one KT=64 tile: 4 k16 blocks, 16 MMA each
__device__ __forceinline__ void mma_tile(uint32_t sb, int warp_m, int warp_n,
                                         int lr, int lc, float acc[2][8][4]) {
#pragma unroll
    for (int kb = 0; kb < 4; ++kb) {
        uint32_t ah[2][4];
#pragma unroll
        for (int mf = 0; mf < 2; ++mf) {
            const uint32_t aoff = (warp_m * 32 + mf * 16 + lr) * A_STRIDE + kb * 32 + lc * 16;
            LDSM_X4(ah[mf], sb + OFF_A + aoff);
        }
#pragma unroll
        for (int ip = 0; ip < 2; ++ip) {
            uint32_t bb[2][4];
#pragma unroll
            for (int ii = 0; ii < 2; ++ii) {
                const int i = ip * 2 + ii;
                const uint32_t boff = (kb * 16 + lr) * B_STRIDE +
                                      (warp_n * 64 + i * 16) * 2 + lc * 16;
                LDSM_X4T(bb[ii], sb + OFF_B + boff);
            }
#pragma unroll
            for (int mf = 0; mf < 2; ++mf)
#pragma unroll
                for (int ii = 0; ii < 2; ++ii) {
                    mma16816(acc[mf][(ip * 2 + ii) * 2],     ah[mf], bb[ii]);
                    mma16816(acc[mf][(ip * 2 + ii) * 2 + 1], ah[mf], bb[ii] + 2);
                }
        }
    }
}

__device__ __forceinline__ void epilogue(float acc[2][8][4], const float* bias,
                                         __half* Xout, float* out, int out_off,
                                         int b0, int warp_m, int warp_n, int lane) {
    const int g = warp_n;
#pragma unroll
    for (int mf = 0; mf < 2; ++mf) {
        const int r0 = warp_m * 32 + mf * 16 + (lane >> 2);
        const int r1 = r0 + 8;
        const float bv0 = bias[r0], bv1 = bias[r1];
        float s0 = 0.f, s1 = 0.f;
#pragma unroll
        for (int nf = 0; nf < 8; ++nf) {
            float* c = acc[mf][nf];
            s0 += c[0] + c[1];
            s1 += c[2] + c[3];
            if (Xout) {
                const int d = nf * 8 + (lane & 3) * 2;
                __half2 v0 = __floats2half2_rn(c[0] + bv0, c[1] + bv0);
                __half2 v1 = __floats2half2_rn(c[2] + bv1, c[3] + bv1);
                *(__half2*)(Xout + (size_t)(b0 + g) * ODIM * DDIM + r0 * DDIM + d) = v0;
                *(__half2*)(Xout + (size_t)(b0 + g) * ODIM * DDIM + r1 * DDIM + d) = v1;
            }
        }
        s0 += __shfl_xor_sync(0xffffffffu, s0, 1);
        s0 += __shfl_xor_sync(0xffffffffu, s0, 2);
        s1 += __shfl_xor_sync(0xffffffffu, s1, 1);
        s1 += __shfl_xor_sync(0xffffffffu, s1, 2);
        if ((lane & 3) == 0) {
            out[(size_t)(b0 + g) * 384 + out_off + r0] = s0 + 64.f * bv0;
            out[(size_t)(b0 + g) * 384 + out_off + r1] = s1 + 64.f * bv1;
        }
    }
}

// ---------------- W convert (fp32 -> fp16, zero padded) ----------------
__global__ void conv_w_kernel(const float* __restrict__ W, __half* __restrict__ hi,
                              int C, int Cpad) {
    int i = blockIdx.x * 256 + threadIdx.x;
    if (i >= ODIM * Cpad) return;
    int o = i / Cpad, cp = i - o * Cpad;
    hi[i] = __float2half_rn((cp < C) ? W[o * C + cp] : 0.f);
}

// ---------------- Layer 1: X0 staged as half, half products ----------------
__global__ __launch_bounds__(THREADS, 2) void cin_l1(
    const float* __restrict__ X0, const __half* __restrict__ W,
    const float* __restrict__ bias, __half* __restrict__ Xout, float* __restrict__ out)
{
    extern __shared__ char smem[];
    constexpr int CPAD_ = 1536, C_ = 1521, NT = CPAD_ / KT;   // 24 tiles

    const int tid = threadIdx.x, wid = tid >> 5, lane = tid & 31;
    const int b0 = blockIdx.x * G;
    const int warp_m = wid >> 1, warp_n = wid & 1;
    const int lr = lane & 15, lc = lane >> 4;
    const int n2 = (tid & 63) * 2, kh = tid >> 6;   // 4 kh groups x 16 k
    const int gg = n2 >> 6, dd = n2 & 63;

    __half* x0h = (__half*)smem;
    const __half* x0_g = x0h + gg * FDIM * DDIM;
    const uint32_t stg = smem_u32(smem + X0H_SZ);

    for (int i = tid; i < G * FDIM * DDIM; i += THREADS)
        x0h[i] = __float2half_rn(X0[(size_t)b0 * FDIM * DDIM + i]);

    float acc[2][8][4];
#pragma unroll
    for (int a = 0; a < 2; ++a)
#pragma unroll
        for (int b = 0; b < 8; ++b)
#pragma unroll
            for (int c = 0; c < 4; ++c) acc[a][b][c] = 0.f;

    auto gen = [&](int t) {
        const uint32_t sb = stg + (t & 1) * STG_SZ;
        char* sbc = smem + X0H_SZ + (t & 1) * STG_SZ;
        const int c0 = t * KT;
        stage_w<CPAD_>(sb, W, c0, tid);
#pragma unroll
        for (int j = 0; j < 16; ++j) {
            const int k = kh * 16 + j;
            const int c = c0 + k;
            __half2 r = __floats2half2_rn(0.f, 0.f);
            if (c < C_) {
                const int h = c / FDIM;
                const int m = c - h * FDIM;
                const __half2 xv = *(const __half2*)(x0_g + h * DDIM + dd);
                const __half2 iv = *(const __half2*)(x0_g + m * DDIM + dd);
                r = __hmul2(xv, iv);
            }
            *(__half2*)(sbc + OFF_B + k * B_STRIDE + n2 * 2) = r;
        }
    };

    __syncthreads();          // x0h ready
    gen(0);
    CP_WAIT0();
    __syncthreads();

    for (int t = 0; t < NT; ++t) {
        if (t + 1 < NT) gen(t + 1);
        mma_tile(stg + (t & 1) * STG_SZ, warp_m, warp_n, lr, lc, acc);
        CP_WAIT0();
        __syncthreads();
    }
    epilogue(acc, bias, Xout, out, 0, b0, warp_m, warp_n, lane);
}

// ---------------- Layers 2/3: Xi (half) staged in smem, x0 half2 broadcast ----------------
__global__ __launch_bounds__(THREADS, 2) void cin_l23(
    const float* __restrict__ X0, const __half* __restrict__ Xi,
    const __half* __restrict__ W,
    const float* __restrict__ bias, __half* __restrict__ Xout,
    float* __restrict__ out, int out_off)
{
    extern __shared__ char smem[];
    constexpr int CPAD_ = 4992, M_ = 128;

    const int tid = threadIdx.x, wid = tid >> 5, lane = tid & 31;
    const int b0 = blockIdx.x * G;
    const int warp_m = wid >> 1, warp_n = wid & 1;
    const int lr = lane & 15, lc = lane >> 4;
    const int n2 = (tid & 63) * 2, kh = tid >> 6;
    const int gg = n2 >> 6, dd = n2 & 63;

    __half* xis = (__half*)smem;
    const __half* xi_g = xis + gg * KT * DDIM;
    const uint32_t stg = smem_u32(smem + XIS_SZ);
    const uint32_t xis_u32 = smem_u32(xis);
    const float* x0_row = X0 + (size_t)(b0 + gg) * FDIM * DDIM + dd;

    float acc[2][8][4];
#pragma unroll
    for (int a = 0; a < 2; ++a)
#pragma unroll
        for (int b = 0; b < 8; ++b)
#pragma unroll
            for (int c = 0; c < 4; ++c) acc[a][b][c] = 0.f;

    auto x0ld = [&](int h) -> float2 {
        return __ldg((const float2*)(x0_row + h * DDIM));
    };

    auto gen = [&](int mb, int h, int buf, float2 xf) {
        const uint32_t sb = stg + buf * STG_SZ;
        char* sbc = smem + XIS_SZ + buf * STG_SZ;
        const int c0 = h * M_ + mb * KT;
        stage_w<CPAD_>(sb, W, c0, tid);
        const __half2 xvh = __floats2half2_rn(xf.x, xf.y);
#pragma unroll
        for (int j = 0; j < 16; ++j) {
            const int k = kh * 16 + j;
            const __half2 iv = *(const __half2*)(xi_g + k * DDIM + dd);
            *(__half2*)(sbc + OFF_B + k * B_STRIDE + n2 * 2) = __hmul2(xvh, iv);
        }
    };

    for (int mb = 0; mb < 2; ++mb) {
        __syncthreads();   // prior mb's gens done reading xis
        // stage Xi m-block (half): G*64*64*2 = 16384B = 1024 x 16B, 4 per thread
#pragma unroll
        for (int it = 0; it < 4; ++it) {
            const int idx = it * THREADS + tid;          // 0..1023
            const int g = idx >> 9, rem = idx & 511;     // 512 chunks per sample
            const __half* src = Xi + (size_t)(b0 + g) * M_ * DDIM + mb * KT * DDIM + rem * 8;
            CP_ASYNC16(xis_u32 + idx * 16, src);
        }
        CP_COMMIT();
        CP_WAIT0();
        __syncthreads();

        float2 xv_n = x0ld(0);
        gen(mb, 0, 0, xv_n);
        xv_n = x0ld(1);
        CP_WAIT0();
        __syncthreads();

        for (int h = 0; h < FDIM; ++h) {
            if (h + 1 < FDIM) {
                const float2 xv_c = xv_n;
                if (h + 2 < FDIM) xv_n = x0ld(h + 2);
                gen(mb, h + 1, (h + 1) & 1, xv_c);
            }
            mma_tile(stg + (h & 1) * STG_SZ, warp_m, warp_n, lr, lc, acc);
            CP_WAIT0();
            __syncthreads();
        }
    }
    epilogue(acc, bias, Xout, out, out_off, b0, warp_m, warp_n, lane);
}

// ---------------- launch ----------------
extern "C" void kernel_launch(void* const* d_in, const int* in_sizes, int n_in,
                              void* d_out, int out_size)
{
    const float* X0 = (const float*)d_in[0];
    const float* W1 = (const float*)d_in[1];
    const float* b1 = (const float*)d_in[2];
    const float* W2 = (const float*)d_in[3];
    const float* b2 = (const float*)d_in[4];
    const float* W3 = (const float*)d_in[5];
    const float* b3 = (const float*)d_in[6];
    float* out = (float*)d_out;

    __half *X1p, *X2p, *W1h, *W2h, *W3h;
    cudaGetSymbolAddress((void**)&X1p, g_X1);
    cudaGetSymbolAddress((void**)&X2p, g_X2);
    cudaGetSymbolAddress((void**)&W1h, g_W1);
    cudaGetSymbolAddress((void**)&W2h, g_W2);
    cudaGetSymbolAddress((void**)&W3h, g_W3);

    cudaFuncSetAttribute(cin_l1,  cudaFuncAttributeMaxDynamicSharedMemorySize, SMEM_L1);
    cudaFuncSetAttribute(cin_l23, cudaFuncAttributeMaxDynamicSharedMemorySize, SMEM_L23);

    conv_w_kernel<<<(ODIM * 1536 + 255) / 256, 256>>>(W1, W1h, 1521, 1536);
    conv_w_kernel<<<(ODIM * 4992 + 255) / 256, 256>>>(W2, W2h, 4992, 4992);
    conv_w_kernel<<<(ODIM * 4992 + 255) / 256, 256>>>(W3, W3h, 4992, 4992);

    cin_l1 <<<BATCH / G, THREADS, SMEM_L1 >>>(X0, W1h, b1, X1p, out);
    cin_l23<<<BATCH / G, THREADS, SMEM_L23>>>(X0, X1p, W2h, b2, X2p, out, 128);
    cin_l23<<<BATCH / G, THREADS, SMEM_L23>>>(X0, X2p, W3h, b3, nullptr, out, 256);
}

// round 11
// speedup vs baseline: 1.7400x; 1.0354x over previous
#include <cuda_runtime.h>
#include <cuda_fp16.h>
#include <cstdint>

#define BATCH 1024
#define FDIM 39
#define DDIM 64
#define ODIM 128
#define G 2
#define KT 64
#define THREADS 256

// ---------------- scratch ----------------
__device__ alignas(16) __half g_X1[BATCH * ODIM * DDIM];
__device__ alignas(16) __half g_X2[BATCH * ODIM * DDIM];
__device__ alignas(16) __half g_W1[ODIM * 1536];
__device__ alignas(16) __half g_W2[ODIM * 4992];
__device__ alignas(16) __half g_W3[ODIM * 4992];

// ---------------- smem layout ----------------
#define A_STRIDE 144
#define B_STRIDE 272
#define OFF_A 0
#define OFF_B 18432
#define STG_SZ 35840
#define X0H_SZ (G * FDIM * DDIM * 2)   // 9984
#define XIS_SZ (G * KT * DDIM * 2)     // 16384
#define SMEM_L1  (X0H_SZ + 2 * STG_SZ)  // 81664
#define SMEM_L23 (XIS_SZ + 2 * STG_SZ)  // 88064

__device__ __forceinline__ uint32_t smem_u32(const void* p) {
    uint32_t a;
    asm("{ .reg .u64 t; cvta.to.shared.u64 t, %1; cvt.u32.u64 %0, t; }" : "=r"(a) : "l"(p));
    return a;
}

#define CP_ASYNC16(dst, src) \
    asm volatile("cp.async.cg.shared.global [%0], [%1], 16;" :: "r"(dst), "l"(src))
#define CP_COMMIT() asm volatile("cp.async.commit_group;")
#define CP_WAIT0()  asm volatile("cp.async.wait_group 0;")

#define LDSM_X4(r, addr) \
    asm volatile("ldmatrix.sync.aligned.m8n8.x4.shared.b16 {%0,%1,%2,%3}, [%4];" \
        : "=r"((r)[0]), "=r"((r)[1]), "=r"((r)[2]), "=r"((r)[3]) : "r"(addr))
#define LDSM_X4T(r, addr) \
    asm volatile("ldmatrix.sync.aligned.m8n8.x4.trans.shared.b16 {%0,%1,%2,%3}, [%4];" \
        : "=r"((r)[0]), "=r"((r)[1]), "=r"((r)[2]), "=r"((r)[3]) : "r"(addr))

__device__ __forceinline__ void mma16816(float* c, const uint32_t* a, const uint32_t* b) {
    asm volatile("mma.sync.aligned.m16n8k16.row.col.f32.f16.f16.f32 "
        "{%0,%1,%2,%3}, {%4,%5,%6,%7}, {%8,%9}, {%0,%1,%2,%3};"
        : "+f"(c[0]), "+f"(c[1]), "+f"(c[2]), "+f"(c[3])
        : "r"(a[0]), "r"(a[1]), "r"(a[2]), "r"(a[3]), "r"(b[0]), "r"(b[1]));
}

// stage W tile: 128 rows x 128B; 2 threads/row, 64B each
template <int CPAD_>
__device__ __forceinline__ void stage_w(uint32_t sb, const __half* W, int c0, int tid) {
    const int wrow = tid >> 1, whalf = tid & 1;
    const char* src = (const char*)(W + (size_t)wrow * CPAD_ + c0) + whalf * 64;
    const uint32_t dst = sb + OFF_A + wrow * A_STRIDE + whalf * 64;
#pragma unroll
    for (int q = 0; q < 4; ++q)
        CP_ASYNC16(dst + q * 16, src + q * 16);
    CP_COMMIT();
}

// MMA over one KT=64 tile with gen-for-next-tile fused per kb block.
template <class GenF>
__device__ __forceinline__ void mma_tile_fused(uint32_t sb, int warp_m, int warp_n,
                                               int lr, int lc, float acc[2][8][4],
                                               GenF gen_part) {
#pragma unroll
    for (int kb = 0; kb < 4; ++kb) {
        gen_part(kb);               // independent stream: feeds buffer t+1
        uint32_t ah[2][4];
#pragma unroll
        for (int mf = 0; mf < 2; ++mf) {
            const uint32_t aoff = (warp_m * 32 + mf * 16 + lr) * A_STRIDE + kb * 32 + lc * 16;
            LDSM_X4(ah[mf], sb + OFF_A + aoff);
        }
#pragma unroll
        for (int ip = 0; ip < 2; ++ip) {
            uint32_t bb[2][4];
#pragma unroll
            for (int ii = 0; ii < 2; ++ii) {
                const int i = ip * 2 + ii;
                const uint32_t boff = (kb * 16 + lr) * B_STRIDE +
                                      (warp_n * 64 + i * 16) * 2 + lc * 16;
                LDSM_X4T(bb[ii], sb + OFF_B + boff);
            }
#pragma unroll
            for (int mf = 0; mf < 2; ++mf)
#pragma unroll
                for (int ii = 0; ii < 2; ++ii) {
                    mma16816(acc[mf][(ip * 2 + ii) * 2],     ah[mf], bb[ii]);
                    mma16816(acc[mf][(ip * 2 + ii) * 2 + 1], ah[mf], bb[ii] + 2);
                }
        }
    }
}

__device__ __forceinline__ void epilogue(float acc[2][8][4], const float* bias,
                                         __half* Xout, float* out, int out_off,
                                         int b0, int warp_m, int warp_n, int lane) {
    const int g = warp_n;
#pragma unroll
    for (int mf = 0; mf < 2; ++mf) {
        const int r0 = warp_m * 32 + mf * 16 + (lane >> 2);
        const int r1 = r0 + 8;
        const float bv0 = bias[r0], bv1 = bias[r1];
        float s0 = 0.f, s1 = 0.f;
#pragma unroll
        for (int nf = 0; nf < 8; ++nf) {
            float* c = acc[mf][nf];
            s0 += c[0] + c[1];
            s1 += c[2] + c[3];
            if (Xout) {
                const int d = nf * 8 + (lane & 3) * 2;
                __half2 v0 = __floats2half2_rn(c[0] + bv0, c[1] + bv0);
                __half2 v1 = __floats2half2_rn(c[2] + bv1, c[3] + bv1);
                *(__half2*)(Xout + (size_t)(b0 + g) * ODIM * DDIM + r0 * DDIM + d) = v0;
                *(__half2*)(Xout + (size_t)(b0 + g) * ODIM * DDIM + r1 * DDIM + d) = v1;
            }
        }
        s0 += __shfl_xor_sync(0xffffffffu, s0, 1);
        s0 += __shfl_xor_sync(0xffffffffu, s0, 2);
        s1 += __shfl_xor_sync(0xffffffffu, s1, 1);
        s1 += __shfl_xor_sync(0xffffffffu, s1, 2);
        if ((lane & 3) == 0) {
            out[(size_t)(b0 + g) * 384 + out_off + r0] = s0 + 64.f * bv0;
            out[(size_t)(b0 + g) * 384 + out_off + r1] = s1 + 64.f * bv1;
        }
    }
}

// ---------------- W convert ----------------
__global__ void conv_w_kernel(const float* __restrict__ W, __half* __restrict__ hi,
                              int C, int Cpad) {
    int i = blockIdx.x * 256 + threadIdx.x;
    if (i >= ODIM * Cpad) return;
    int o = i / Cpad, cp = i - o * Cpad;
    hi[i] = __float2half_rn((cp < C) ? W[o * C + cp] : 0.f);
}

// ---------------- Layer 1 ----------------
__global__ __launch_bounds__(THREADS, 2) void cin_l1(
    const float* __restrict__ X0, const __half* __restrict__ W,
    const float* __restrict__ bias, __half* __restrict__ Xout, float* __restrict__ out)
{
    extern __shared__ char smem[];
    constexpr int CPAD_ = 1536, C_ = 1521, NT = CPAD_ / KT;   // 24 tiles

    const int tid = threadIdx.x, wid = tid >> 5, lane = tid & 31;
    const int b0 = blockIdx.x * G;
    const int warp_m = wid >> 1, warp_n = wid & 1;
    const int lr = lane & 15, lc = lane >> 4;
    const int n2 = (tid & 63) * 2, kh = tid >> 6;
    const int gg = n2 >> 6, dd = n2 & 63;

    __half* x0h = (__half*)smem;
    const __half* x0_g = x0h + gg * FDIM * DDIM;
    const uint32_t stg = smem_u32(smem + X0H_SZ);

    for (int i = tid; i < G * FDIM * DDIM; i += THREADS)
        x0h[i] = __float2half_rn(X0[(size_t)b0 * FDIM * DDIM + i]);

    float acc[2][8][4];
#pragma unroll
    for (int a = 0; a < 2; ++a)
#pragma unroll
        for (int b = 0; b < 8; ++b)
#pragma unroll
            for (int c = 0; c < 4; ++c) acc[a][b][c] = 0.f;

    // full gen of tile t (used only for the prologue tile 0)
    auto gen_full = [&](int t) {
        const uint32_t sb = stg + (t & 1) * STG_SZ;
        char* sbc = smem + X0H_SZ + (t & 1) * STG_SZ;
        const int c0 = t * KT;
        stage_w<CPAD_>(sb, W, c0, tid);
#pragma unroll
        for (int j = 0; j < 16; ++j) {
            const int k = kh * 16 + j;
            const int c = c0 + k;
            __half2 r = __floats2half2_rn(0.f, 0.f);
            if (c < C_) {
                const int h = c / FDIM;
                const int m = c - h * FDIM;
                r = __hmul2(*(const __half2*)(x0_g + h * DDIM + dd),
                            *(const __half2*)(x0_g + m * DDIM + dd));
            }
            *(__half2*)(sbc + OFF_B + k * B_STRIDE + n2 * 2) = r;
        }
    };

    __syncthreads();
    gen_full(0);
    CP_WAIT0();
    __syncthreads();

    for (int t = 0; t < NT; ++t) {
        const bool dg = (t + 1 < NT);
        const int tn = t + 1;
        const uint32_t sbn = stg + (tn & 1) * STG_SZ;
        char* sbcn = smem + X0H_SZ + (tn & 1) * STG_SZ;
        const int c0n = tn * KT;

        auto gen_part = [&](int kb) {
            if (!dg) return;
            if (kb == 0) stage_w<CPAD_>(sbn, W, c0n, tid);
            const int jb = kb * 4;
            int c = c0n + kh * 16 + jb;
            int h = c / FDIM;                  // 1 division per quarter
            int m = c - h * FDIM;
#pragma unroll
            for (int j = 0; j < 4; ++j) {
                __half2 r = __floats2half2_rn(0.f, 0.f);
                if (c < C_)
                    r = __hmul2(*(const __half2*)(x0_g + h * DDIM + dd),
                                *(const __half2*)(x0_g + m * DDIM + dd));
                *(__half2*)(sbcn + OFF_B + (kh * 16 + jb + j) * B_STRIDE + n2 * 2) = r;
                ++c; ++m;
                if (m == FDIM) { m = 0; ++h; }
            }
        };

        mma_tile_fused(stg + (t & 1) * STG_SZ, warp_m, warp_n, lr, lc, acc, gen_part);
        CP_WAIT0();
        __syncthreads();
    }
    epilogue(acc, bias, Xout, out, 0, b0, warp_m, warp_n, lane);
}

// ---------------- Layers 2/3 ----------------
__global__ __launch_bounds__(THREADS, 2) void cin_l23(
    const float* __restrict__ X0, const __half* __restrict__ Xi,
    const __half* __restrict__ W,
    const float* __restrict__ bias, __half* __restrict__ Xout,
    float* __restrict__ out, int out_off)
{
    extern __shared__ char smem[];
    constexpr int CPAD_ = 4992, M_ = 128;

    const int tid = threadIdx.x, wid = tid >> 5, lane = tid & 31;
    const int b0 = blockIdx.x * G;
    const int warp_m = wid >> 1, warp_n = wid & 1;
    const int lr = lane & 15, lc = lane >> 4;
    const int n2 = (tid & 63) * 2, kh = tid >> 6;
    const int gg = n2 >> 6, dd = n2 & 63;

    __half* xis = (__half*)smem;
    const __half* xi_g = xis + gg * KT * DDIM;
    const uint32_t stg = smem_u32(smem + XIS_SZ);
    const uint32_t xis_u32 = smem_u32(xis);
    const float* x0_row = X0 + (size_t)(b0 + gg) * FDIM * DDIM + dd;

    float acc[2][8][4];
#pragma unroll
    for (int a = 0; a < 2; ++a)
#pragma unroll
        for (int b = 0; b < 8; ++b)
#pragma unroll
            for (int c = 0; c < 4; ++c) acc[a][b][c] = 0.f;

    auto x0ld = [&](int h) -> float2 {
        return __ldg((const float2*)(x0_row + h * DDIM));
    };

    auto gen_full = [&](int mb, int h, int buf, float2 xf) {
        const uint32_t sb = stg + buf * STG_SZ;
        char* sbc = smem + XIS_SZ + buf * STG_SZ;
        stage_w<CPAD_>(sb, W, h * M_ + mb * KT, tid);
        const __half2 xvh = __floats2half2_rn(xf.x, xf.y);
#pragma unroll
        for (int j = 0; j < 16; ++j) {
            const int k = kh * 16 + j;
            const __half2 iv = *(const __half2*)(xi_g + k * DDIM + dd);
            *(__half2*)(sbc + OFF_B + k * B_STRIDE + n2 * 2) = __hmul2(xvh, iv);
        }
    };

    for (int mb = 0; mb < 2; ++mb) {
        __syncthreads();
#pragma unroll
        for (int it = 0; it < 4; ++it) {
            const int idx = it * THREADS + tid;
            const int g = idx >> 9, rem = idx & 511;
            const __half* src = Xi + (size_t)(b0 + g) * M_ * DDIM + mb * KT * DDIM + rem * 8;
            CP_ASYNC16(xis_u32 + idx * 16, src);
        }
        CP_COMMIT();
        CP_WAIT0();
        __syncthreads();

        float2 xv0 = x0ld(0);
        gen_full(mb, 0, 0, xv0);
        float2 xv_n = x0ld(1);
        CP_WAIT0();
        __syncthreads();

        for (int h = 0; h < FDIM; ++h) {
            const bool dg = (h + 1 < FDIM);
            const int hn = h + 1;
            const uint32_t sbn = stg + (hn & 1) * STG_SZ;
            char* sbcn = smem + XIS_SZ + (hn & 1) * STG_SZ;
            const __half2 xvh = __floats2half2_rn(xv_n.x, xv_n.y);
            if (h + 2 < FDIM) xv_n = x0ld(h + 2);   // prefetch for next iter

            auto gen_part = [&](int kb) {
                if (!dg) return;
                if (kb == 0) stage_w<CPAD_>(sbn, W, hn * M_ + mb * KT, tid);
                const int jb = kb * 4;
#pragma unroll
                for (int j = 0; j < 4; ++j) {
                    const int k = kh * 16 + jb + j;
                    const __half2 iv = *(const __half2*)(xi_g + k * DDIM + dd);
                    *(__half2*)(sbcn + OFF_B + k * B_STRIDE + n2 * 2) = __hmul2(xvh, iv);
                }
            };

            mma_tile_fused(stg + (h & 1) * STG_SZ, warp_m, warp_n, lr, lc, acc, gen_part);
            CP_WAIT0();
            __syncthreads();
        }
    }
    epilogue(acc, bias, Xout, out, out_off, b0, warp_m, warp_n, lane);
}

// ---------------- launch ----------------
extern "C" void kernel_launch(void* const* d_in, const int* in_sizes, int n_in,
                              void* d_out, int out_size)
{
    const float* X0 = (const float*)d_in[0];
    const float* W1 = (const float*)d_in[1];
    const float* b1 = (const float*)d_in[2];
    const float* W2 = (const float*)d_in[3];
    const float* b2 = (const float*)d_in[4];
    const float* W3 = (const float*)d_in[5];
    const float* b3 = (const float*)d_in[6];
    float* out = (float*)d_out;

    __half *X1p, *X2p, *W1h, *W2h, *W3h;
    cudaGetSymbolAddress((void**)&X1p, g_X1);
    cudaGetSymbolAddress((void**)&X2p, g_X2);
    cudaGetSymbolAddress((void**)&W1h, g_W1);
    cudaGetSymbolAddress((void**)&W2h, g_W2);
    cudaGetSymbolAddress((void**)&W3h, g_W3);

    cudaFuncSetAttribute(cin_l1,  cudaFuncAttributeMaxDynamicSharedMemorySize, SMEM_L1);
    cudaFuncSetAttribute(cin_l23, cudaFuncAttributeMaxDynamicSharedMemorySize, SMEM_L23);

    conv_w_kernel<<<(ODIM * 1536 + 255) / 256, 256>>>(W1, W1h, 1521, 1536);
    conv_w_kernel<<<(ODIM * 4992 + 255) / 256, 256>>>(W2, W2h, 4992, 4992);
    conv_w_kernel<<<(ODIM * 4992 + 255) / 256, 256>>>(W3, W3h, 4992, 4992);

    cin_l1 <<<BATCH / G, THREADS, SMEM_L1 >>>(X0, W1h, b1, X1p, out);
    cin_l23<<<BATCH / G, THREADS, SMEM_L23>>>(X0, X1p, W2h, b2, X2p, out, 128);
    cin_l23<<<BATCH / G, THREADS, SMEM_L23>>>(X0, X2p, W3h, b3, nullptr, out, 256);
}